// round 8
// baseline (speedup 1.0000x reference)
#include <cuda_runtime.h>
#include <math.h>

#define NN      8192
#define KZ      20
#define PDIM    20
#define NVZ     64
#define NUMPROT 20
#define FZ      256
#define NFEAT   2000
#define NDIST   100
#define NSLICE  4
#define SLICE   2048

// output layout: tuple members concatenated, float32
#define OFF_POS (NN*(FZ+NVZ))
#define OFF_NP  (OFF_POS + NN*3)
#define OFF_ND  (OFF_NP  + NN*KZ*3)
#define OFF_EI  (OFF_ND  + NN*KZ*PDIM)
#define OFF_FEI (OFF_EI  + NN*KZ)

// device scratch (allocation-free rule -> static globals)
__device__ float4 g_pos4[NN];
__device__ float4 g_ncac[NN*3];
__device__ int    g_edge[NN*KZ];
__device__ float  g_dist[NN*NDIST];
__device__ float  g_wt[NFEAT*NVZ];
__device__ float  g_enc[NN*NFEAT];
__device__ float  g_freq[PDIM/2];
__device__ int    g_mask_kind;
__device__ float  g_pdist[NN*NSLICE*KZ];
__device__ int    g_pidx [NN*NSLICE*KZ];

// ---------------------------------------------------------------------------
// FMA-pipe sincos (abs err < 4e-6 for |x| < 25)
// ---------------------------------------------------------------------------
__device__ __forceinline__ void sincos_poly(float x, float& so, float& co) {
    float q = rintf(x * 0.6366197723675814f);
    int iq = (int)q;
    float r = fmaf(-q, 1.57079637050628662109375f, x);
    r = fmaf(-q, -4.37113900018624283e-8f, r);
    float r2 = r * r;
    float ps = fmaf(-1.9841270114e-4f, r2, 8.3333337680e-3f);
    ps = fmaf(ps, r2, -1.6666667163e-1f);
    float sinr = fmaf(ps * r2, r, r);
    float pc = fmaf(-1.3888889225e-3f, r2, 4.1666667908e-2f);
    pc = fmaf(pc, r2, -0.5f);
    float cosr = fmaf(pc, r2, 1.0f);
    int qq = iq & 3;
    float s_ = (qq & 1) ? cosr : sinr;
    float c_ = (qq & 1) ? sinr : cosr;
    if (qq == 1 || qq == 2) c_ = -c_;
    if (qq >= 2) s_ = -s_;
    so = s_; co = c_;
}

// ---------------------------------------------------------------------------
// Classify prot_mask storage: 0=int32(0/1 words), 1=uint8, 2=float32.
// Also compute sinusoidal freqs 50^(-t/10) in fp64.
// ---------------------------------------------------------------------------
__global__ void detect_kernel(const unsigned int* __restrict__ m) {
    __shared__ int red[256];
    int t = threadIdx.x;
    int code = 0;
    for (int i = t; i < 2048; i += 256) {
        unsigned w = m[i];
        if (w == 0x3F800000u) code = 2;
        else if (w != 0u && w != 1u) code = max(code, 1);
    }
    red[t] = code; __syncthreads();
    for (int s = 128; s > 0; s >>= 1) {
        if (t < s) red[t] = max(red[t], red[t+s]);
        __syncthreads();
    }
    if (t == 0) g_mask_kind = red[0];
    if (t < PDIM/2) g_freq[t] = (float)exp(-0.39120230054281463 * (double)t);
}

// ne_weight (64,2000) -> g_wt (2000,64)
__global__ void wt_kernel(const float* __restrict__ w) {
    int idx = blockIdx.x*256 + threadIdx.x;
    if (idx >= NVZ*NFEAT) return;
    int o = idx / NFEAT, f = idx - o*NFEAT;
    g_wt[f*NVZ + o] = w[idx];
}

// per-node: pos4 (pos + |p|^2, plain asc rounding), ncac atoms, positions out
__global__ void setup_kernel(const float* __restrict__ aff,
                             const float* __restrict__ lit,
                             const void*  __restrict__ maskp,
                             float* __restrict__ out) {
    int i = blockIdx.x*256 + threadIdx.x;
    if (i >= NN) return;
    const float* A = aff + i*12;
    float r0=A[0], r1=A[1], r2=A[2],  tx=A[3];
    float r3=A[4], r4=A[5], r5=A[6],  ty=A[7];
    float r6=A[8], r7=A[9], r8=A[10], tz=A[11];
    float n2 = __fadd_rn(__fadd_rn(__fmul_rn(tx,tx), __fmul_rn(ty,ty)),
                         __fmul_rn(tz,tz));
    g_pos4[i] = make_float4(tx,ty,tz,n2);
    out[OFF_POS+i*3+0]=tx; out[OFF_POS+i*3+1]=ty; out[OFF_POS+i*3+2]=tz;

    int kind = g_mask_kind;
    bool mk;
    if (kind == 1)      mk = ((const unsigned char*)maskp)[i] != 0;
    else if (kind == 2) mk = ((const float*)maskp)[i] != 0.0f;
    else                mk = ((const int*)maskp)[i] != 0;
    const float* L = lit + (mk ? 0 : NUMPROT)*9;
    #pragma unroll
    for (int a = 0; a < 3; a++) {
        float lx=L[a*3+0], ly=L[a*3+1], lz=L[a*3+2];
        float px = fmaf(r0,lx, fmaf(r1,ly, r2*lz)) + tx;
        float py = fmaf(r3,lx, fmaf(r4,ly, r5*lz)) + ty;
        float pz = fmaf(r6,lx, fmaf(r7,ly, r8*lz)) + tz;
        g_ncac[i*3+a] = make_float4(px,py,pz,0.f);
    }
}

// ---------------------------------------------------------------------------
// kNN partial pass: block = 128 queries x 1 candidate slice (2048 cands).
//   dot = fma(z,z', fma(y,y', rn(x*x')))                 (asc-FMA, cublas)
//   d2  = rn( n2i + fma(-2, dot, n2j) )                  (bias-epilogue assoc)
// strict < admission + stable insertion (lower-index ties), j ascending.
// ---------------------------------------------------------------------------
__global__ void knn_part_kernel() {
    __shared__ float4 tile[SLICE];
    int q = blockIdx.x*128 + threadIdx.x;
    int s = blockIdx.y;
    for (int i = threadIdx.x; i < SLICE; i += 128) tile[i] = g_pos4[s*SLICE + i];
    __syncthreads();
    float4 P = g_pos4[q];
    const float INF = __int_as_float(0x7f800000);
    float dist[KZ]; int idx[KZ];
    #pragma unroll
    for (int t = 0; t < KZ; t++) { dist[t] = INF; idx[t] = 0; }

    #pragma unroll 4
    for (int jj = 0; jj < SLICE; jj++) {
        float4 c = tile[jj];
        int j = s*SLICE + jj;
        float dot = __fmaf_rn(P.z, c.z,
                    __fmaf_rn(P.y, c.y, __fmul_rn(P.x, c.x)));
        float d2  = __fadd_rn(P.w, __fmaf_rn(-2.0f, dot, c.w));
        if (d2 < dist[KZ-1] && j != q) {
            float v = d2; int vi = j;
            #pragma unroll
            for (int t = 0; t < KZ; t++) {
                if (v < dist[t]) {
                    float td = dist[t]; int ti = idx[t];
                    dist[t] = v; idx[t] = vi;
                    v = td; vi = ti;
                }
            }
        }
    }
    int base = (q*NSLICE + s)*KZ;
    #pragma unroll
    for (int t = 0; t < KZ; t++) { g_pdist[base+t] = dist[t]; g_pidx[base+t] = idx[t]; }
}

// Merge per-slice lists: slices ascending (ascending index ranges), ranks
// ascending, strict < insertion — exactly reproduces the monolithic stable
// lower-index-first pass.
__global__ void knn_merge_kernel(float* __restrict__ out) {
    int q = blockIdx.x*256 + threadIdx.x;
    const float INF = __int_as_float(0x7f800000);
    float dist[KZ]; int idx[KZ];
    #pragma unroll
    for (int t = 0; t < KZ; t++) { dist[t] = INF; idx[t] = 0; }
    for (int s = 0; s < NSLICE; s++) {
        int base = (q*NSLICE + s)*KZ;
        #pragma unroll
        for (int r = 0; r < KZ; r++) {
            float v = g_pdist[base+r];
            if (v > 3e38f) break;
            if (v < dist[KZ-1]) {
                int vi = g_pidx[base+r];
                #pragma unroll
                for (int t = 0; t < KZ; t++) {
                    if (v < dist[t]) {
                        float td = dist[t]; int ti = idx[t];
                        dist[t] = v; idx[t] = vi;
                        v = td; vi = ti;
                    }
                }
            } else break;  // ranks ascending: no later rank can qualify
        }
    }
    #pragma unroll
    for (int k = 0; k < KZ; k++) {
        g_edge[q*KZ+k] = idx[k];
        out[OFF_EI  + q*KZ + k] = (float)idx[k];
        out[OFF_FEI + q*KZ + k] = (float)idx[k];
        out[OFF_FEI + NN*KZ + q*KZ + k] = (float)q;
    }
}

// ---------------------------------------------------------------------------
// Per-edge geometry: neighbour_positions, neighbour distance encoding (poly),
// and the 100 backbone distances per node into g_dist.
// ---------------------------------------------------------------------------
__global__ void geom_kernel(const float* __restrict__ aff,
                            float* __restrict__ out) {
    int n = blockIdx.x;
    int k = threadIdx.x;
    if (k >= KZ) return;
    const float* A = aff + n*12;
    float r0=A[0], r1=A[1], r2=A[2],  tx=A[3];
    float r3=A[4], r4=A[5], r5=A[6],  ty=A[7];
    float r6=A[8], r7=A[9], r8=A[10], tz=A[11];
    int j = g_edge[n*KZ+k];
    float4 nb = g_pos4[j];
    float vx = nb.x - tx, vy = nb.y - ty, vz = nb.z - tz;
    float ex = fmaf(r0,vx, fmaf(r3,vy, r6*vz));
    float ey = fmaf(r1,vx, fmaf(r4,vy, r7*vz));
    float ez = fmaf(r2,vx, fmaf(r5,vy, r8*vz));
    int eb = (n*KZ+k)*3;
    out[OFF_NP+eb+0]=ex; out[OFF_NP+eb+1]=ey; out[OFF_NP+eb+2]=ez;
    float nrm = sqrtf(fmaf(ex,ex, fmaf(ey,ey, ez*ez)));
    int db = (n*KZ+k)*PDIM;
    #pragma unroll
    for (int t = 0; t < PDIM/2; t++) {
        float sv, cv;
        sincos_poly(nrm * g_freq[t], sv, cv);
        out[OFF_ND+db+t]    = sv;
        out[OFF_ND+db+10+t] = cv;
    }
    float4 ca = g_ncac[n*3+1], np = g_ncac[n*3+0], cp = g_ncac[n*3+2];
    #pragma unroll
    for (int a = 0; a < 3; a++) {
        float4 p = g_ncac[j*3+a];
        float dx=p.x-ca.x, dy=p.y-ca.y, dz=p.z-ca.z;
        g_dist[n*NDIST + k*3 + a] = sqrtf(fmaf(dx,dx, fmaf(dy,dy, dz*dz)));
    }
    {
        float4 p = g_ncac[j*3+2];
        float dx=p.x-np.x, dy=p.y-np.y, dz=p.z-np.z;
        g_dist[n*NDIST + 60 + k] = sqrtf(fmaf(dx,dx, fmaf(dy,dy, dz*dz)));
        float4 p2 = g_ncac[j*3+0];
        float ex2=p2.x-cp.x, ey2=p2.y-cp.y, ez2=p2.z-cp.z;
        g_dist[n*NDIST + 80 + k] = sqrtf(fmaf(ex2,ex2, fmaf(ey2,ey2, ez2*ez2)));
    }
}

// enc[n][d*20 + t] = sin(dist*f_t), enc[n][d*20+10+t] = cos(dist*f_t)
__global__ void enc_kernel() {
    __shared__ float dl[NDIST];
    __shared__ float fl[PDIM/2];
    int n = blockIdx.x;
    int tid = threadIdx.x;
    if (tid < NDIST) dl[tid] = g_dist[n*NDIST+tid];
    if (tid >= 128 && tid < 128+PDIM/2) fl[tid-128] = g_freq[tid-128];
    __syncthreads();
    for (int f = tid; f < NDIST*(PDIM/2); f += 256) {
        int d = f / 10;
        int t = f - d*10;
        float sv, cv;
        sincos_poly(dl[d] * fl[t], sv, cv);
        g_enc[n*NFEAT + d*20 + t]      = sv;
        g_enc[n*NFEAT + d*20 + 10 + t] = cv;
    }
}

// copy x (8192x256) into x_ne rows (stride 320), vectorized
__global__ void copyx_kernel(const float* __restrict__ x, float* __restrict__ out) {
    int i = blockIdx.x*256 + threadIdx.x;
    if (i >= NN*64) return;
    int n = i >> 6, c = i & 63;
    float4 v = ((const float4*)x)[i];
    ((float4*)out)[n*80 + c] = v;
}

// ---------------------------------------------------------------------------
// GEMM: C(8192x64) = g_enc(8192x2000) @ g_wt(2000x64)
// ---------------------------------------------------------------------------
#define BK 16
__global__ void gemm_kernel(float* __restrict__ out) {
    __shared__ float As[BK][68];
    __shared__ float Bs[BK][64];
    int tid = threadIdx.x;
    int tx = tid & 15, ty = tid >> 4;
    int m0 = blockIdx.x * 64;
    float acc[4][4];
    #pragma unroll
    for (int a = 0; a < 4; a++)
        #pragma unroll
        for (int b = 0; b < 4; b++) acc[a][b] = 0.f;

    const float* Ag = g_enc + (size_t)m0 * NFEAT;
    for (int kt = 0; kt < NFEAT; kt += BK) {
        #pragma unroll
        for (int i = 0; i < 4; i++) {
            int e = tid + i*256;
            int m = e >> 4, kk = e & 15;
            As[kk][m] = Ag[m*NFEAT + kt + kk];
        }
        #pragma unroll
        for (int i = 0; i < 4; i++) {
            int e = tid + i*256;
            int kk = e >> 6, nn = e & 63;
            Bs[kk][nn] = g_wt[(kt+kk)*NVZ + nn];
        }
        __syncthreads();
        #pragma unroll
        for (int kk = 0; kk < BK; kk++) {
            float4 a = *(const float4*)&As[kk][ty*4];
            float4 b = *(const float4*)&Bs[kk][tx*4];
            float av[4] = {a.x,a.y,a.z,a.w};
            float bv[4] = {b.x,b.y,b.z,b.w};
            #pragma unroll
            for (int i = 0; i < 4; i++)
                #pragma unroll
                for (int jj = 0; jj < 4; jj++)
                    acc[i][jj] = fmaf(av[i], bv[jj], acc[i][jj]);
        }
        __syncthreads();
    }
    #pragma unroll
    for (int i = 0; i < 4; i++) {
        int m = m0 + ty*4 + i;
        #pragma unroll
        for (int jj = 0; jj < 4; jj++)
            out[m*(FZ+NVZ) + FZ + tx*4 + jj] = acc[i][jj];
    }
}

extern "C" void kernel_launch(void* const* d_in, const int* in_sizes, int n_in,
                              void* d_out, int out_size) {
    const float* x    = (const float*)d_in[0];
    const float* aff  = (const float*)d_in[1];
    const float* nw   = (const float*)d_in[2];
    const float* lit  = (const float*)d_in[3];
    const void*  mask = d_in[4];
    float* out = (float*)d_out;

    detect_kernel<<<1, 256>>>((const unsigned int*)mask);
    wt_kernel<<<(NVZ*NFEAT + 255)/256, 256>>>(nw);
    setup_kernel<<<(NN+255)/256, 256>>>(aff, lit, mask, out);
    knn_part_kernel<<<dim3(NN/128, NSLICE), 128>>>();
    knn_merge_kernel<<<NN/256, 256>>>(out);
    geom_kernel<<<NN, 32>>>(aff, out);
    enc_kernel<<<NN, 256>>>();
    copyx_kernel<<<(NN*64 + 255)/256, 256>>>(x, out);
    gemm_kernel<<<NN/64, 256>>>(out);
}

// round 9
// speedup vs baseline: 2.0314x; 2.0314x over previous
#include <cuda_runtime.h>
#include <math.h>

#define NN      8192
#define KZ      20
#define PDIM    20
#define NVZ     64
#define NUMPROT 20
#define FZ      256
#define NFEAT   2000
#define NDIST   100

// output layout: tuple members concatenated, float32
#define OFF_POS (NN*(FZ+NVZ))
#define OFF_NP  (OFF_POS + NN*3)
#define OFF_ND  (OFF_NP  + NN*KZ*3)
#define OFF_EI  (OFF_ND  + NN*KZ*PDIM)
#define OFF_FEI (OFF_EI  + NN*KZ)

// device scratch (allocation-free rule -> static globals)
__device__ float4 g_pos4[NN];
__device__ float4 g_ncac[NN*3];
__device__ int    g_edge[NN*KZ];
__device__ float  g_dist[NN*NDIST];
__device__ float  g_wt[NFEAT*NVZ];
__device__ float  g_enc[NN*NFEAT];
__device__ float  g_freq[PDIM/2];
__device__ int    g_mask_kind;

// ---------------------------------------------------------------------------
// FMA-pipe sincos (abs err < 4e-6 for |x| < 25)
// ---------------------------------------------------------------------------
__device__ __forceinline__ void sincos_poly(float x, float& so, float& co) {
    float q = rintf(x * 0.6366197723675814f);
    int iq = (int)q;
    float r = fmaf(-q, 1.57079637050628662109375f, x);
    r = fmaf(-q, -4.37113900018624283e-8f, r);
    float r2 = r * r;
    float ps = fmaf(-1.9841270114e-4f, r2, 8.3333337680e-3f);
    ps = fmaf(ps, r2, -1.6666667163e-1f);
    float sinr = fmaf(ps * r2, r, r);
    float pc = fmaf(-1.3888889225e-3f, r2, 4.1666667908e-2f);
    pc = fmaf(pc, r2, -0.5f);
    float cosr = fmaf(pc, r2, 1.0f);
    int qq = iq & 3;
    float s_ = (qq & 1) ? cosr : sinr;
    float c_ = (qq & 1) ? sinr : cosr;
    if (qq == 1 || qq == 2) c_ = -c_;
    if (qq >= 2) s_ = -s_;
    so = s_; co = c_;
}

// ---------------------------------------------------------------------------
// Classify prot_mask storage: 0=int32(0/1 words), 1=uint8, 2=float32.
// Also compute sinusoidal freqs 50^(-t/10) in fp64.
// ---------------------------------------------------------------------------
__global__ void detect_kernel(const unsigned int* __restrict__ m) {
    __shared__ int red[256];
    int t = threadIdx.x;
    int code = 0;
    for (int i = t; i < 2048; i += 256) {
        unsigned w = m[i];
        if (w == 0x3F800000u) code = 2;
        else if (w != 0u && w != 1u) code = max(code, 1);
    }
    red[t] = code; __syncthreads();
    for (int s = 128; s > 0; s >>= 1) {
        if (t < s) red[t] = max(red[t], red[t+s]);
        __syncthreads();
    }
    if (t == 0) g_mask_kind = red[0];
    if (t < PDIM/2) g_freq[t] = (float)exp(-0.39120230054281463 * (double)t);
}

// ne_weight (64,2000) -> g_wt (2000,64)
__global__ void wt_kernel(const float* __restrict__ w) {
    int idx = blockIdx.x*256 + threadIdx.x;
    if (idx >= NVZ*NFEAT) return;
    int o = idx / NFEAT, f = idx - o*NFEAT;
    g_wt[f*NVZ + o] = w[idx];
}

// per-node: pos4 (pos + |p|^2, plain asc rounding), ncac atoms, positions out
__global__ void setup_kernel(const float* __restrict__ aff,
                             const float* __restrict__ lit,
                             const void*  __restrict__ maskp,
                             float* __restrict__ out) {
    int i = blockIdx.x*256 + threadIdx.x;
    if (i >= NN) return;
    const float* A = aff + i*12;
    float r0=A[0], r1=A[1], r2=A[2],  tx=A[3];
    float r3=A[4], r4=A[5], r5=A[6],  ty=A[7];
    float r6=A[8], r7=A[9], r8=A[10], tz=A[11];
    float n2 = __fadd_rn(__fadd_rn(__fmul_rn(tx,tx), __fmul_rn(ty,ty)),
                         __fmul_rn(tz,tz));
    g_pos4[i] = make_float4(tx,ty,tz,n2);
    out[OFF_POS+i*3+0]=tx; out[OFF_POS+i*3+1]=ty; out[OFF_POS+i*3+2]=tz;

    int kind = g_mask_kind;
    bool mk;
    if (kind == 1)      mk = ((const unsigned char*)maskp)[i] != 0;
    else if (kind == 2) mk = ((const float*)maskp)[i] != 0.0f;
    else                mk = ((const int*)maskp)[i] != 0;
    const float* L = lit + (mk ? 0 : NUMPROT)*9;
    #pragma unroll
    for (int a = 0; a < 3; a++) {
        float lx=L[a*3+0], ly=L[a*3+1], lz=L[a*3+2];
        float px = fmaf(r0,lx, fmaf(r1,ly, r2*lz)) + tx;
        float py = fmaf(r3,lx, fmaf(r4,ly, r5*lz)) + ty;
        float pz = fmaf(r6,lx, fmaf(r7,ly, r8*lz)) + tz;
        g_ncac[i*3+a] = make_float4(px,py,pz,0.f);
    }
}

// ---------------------------------------------------------------------------
// kNN: warp-cooperative ballot-insert top-20. One warp per query; the top-20
// list lives lane-distributed (slot l in lane l), sorted lexicographically by
// (d2, index). d2 bits are FROZEN from the passing config:
//   dot = fma(z,z', fma(y,y', rn(x*x')));  d2 = rn(n2i + fma(-2,dot,n2j))
// Lexicographic order makes the result scan-order invariant and identical to
// the strict-<, ascending-j stable insertion that passed (= lax.top_k).
// ---------------------------------------------------------------------------
#define KTILE 2048
__global__ void __launch_bounds__(256) knn_kernel(float* __restrict__ out) {
    __shared__ float4 tile[KTILE];
    const unsigned FULL = 0xffffffffu;
    int warp = threadIdx.x >> 5;
    int lane = threadIdx.x & 31;
    int q = blockIdx.x*8 + warp;
    float4 P = g_pos4[q];
    const float INF = __int_as_float(0x7f800000);
    float dist = INF;
    int   idx  = 0x7FFFFFFF;

    for (int t0 = 0; t0 < NN; t0 += KTILE) {
        __syncthreads();
        for (int i = threadIdx.x; i < KTILE; i += 256) tile[i] = g_pos4[t0+i];
        __syncthreads();
        for (int b = 0; b < KTILE; b += 32) {
            int j = t0 + b + lane;
            float4 c = tile[b + lane];
            float dot = __fmaf_rn(P.z, c.z,
                        __fmaf_rn(P.y, c.y, __fmul_rn(P.x, c.x)));
            float d2  = __fadd_rn(P.w, __fmaf_rn(-2.0f, dot, c.w));
            float d19 = __shfl_sync(FULL, dist, 19);
            int   i19 = __shfl_sync(FULL, idx, 19);
            bool qual = (j != q) &&
                        (d2 < d19 || (d2 == d19 && j < i19));
            unsigned bal = __ballot_sync(FULL, qual);
            while (bal) {
                int src = __ffs(bal) - 1; bal &= bal - 1;
                float cd = __shfl_sync(FULL, d2, src);
                int   ci = t0 + b + src;
                // position among current 20 slots (list may have changed)
                unsigned mlt = __ballot_sync(FULL,
                    (dist < cd) || (dist == cd && idx < ci)) & 0xFFFFFu;
                int p = __popc(mlt);
                if (p < 20) {
                    float nd = __shfl_up_sync(FULL, dist, 1);
                    int   ni = __shfl_up_sync(FULL, idx, 1);
                    if (lane >= p && lane < 20) {
                        dist = (lane == p) ? cd : nd;
                        idx  = (lane == p) ? ci : ni;
                    }
                }
            }
        }
    }
    if (lane < KZ) {
        g_edge[q*KZ+lane] = idx;
        out[OFF_EI  + q*KZ + lane] = (float)idx;
        out[OFF_FEI + q*KZ + lane] = (float)idx;
        out[OFF_FEI + NN*KZ + q*KZ + lane] = (float)q;
    }
}

// ---------------------------------------------------------------------------
// Per-edge geometry: neighbour_positions, neighbour distance encoding (poly),
// and the 100 backbone distances per node into g_dist.
// ---------------------------------------------------------------------------
__global__ void geom_kernel(const float* __restrict__ aff,
                            float* __restrict__ out) {
    int n = blockIdx.x;
    int k = threadIdx.x;
    if (k >= KZ) return;
    const float* A = aff + n*12;
    float r0=A[0], r1=A[1], r2=A[2],  tx=A[3];
    float r3=A[4], r4=A[5], r5=A[6],  ty=A[7];
    float r6=A[8], r7=A[9], r8=A[10], tz=A[11];
    int j = g_edge[n*KZ+k];
    float4 nb = g_pos4[j];
    float vx = nb.x - tx, vy = nb.y - ty, vz = nb.z - tz;
    float ex = fmaf(r0,vx, fmaf(r3,vy, r6*vz));
    float ey = fmaf(r1,vx, fmaf(r4,vy, r7*vz));
    float ez = fmaf(r2,vx, fmaf(r5,vy, r8*vz));
    int eb = (n*KZ+k)*3;
    out[OFF_NP+eb+0]=ex; out[OFF_NP+eb+1]=ey; out[OFF_NP+eb+2]=ez;
    float nrm = sqrtf(fmaf(ex,ex, fmaf(ey,ey, ez*ez)));
    int db = (n*KZ+k)*PDIM;
    #pragma unroll
    for (int t = 0; t < PDIM/2; t++) {
        float sv, cv;
        sincos_poly(nrm * g_freq[t], sv, cv);
        out[OFF_ND+db+t]    = sv;
        out[OFF_ND+db+10+t] = cv;
    }
    float4 ca = g_ncac[n*3+1], np = g_ncac[n*3+0], cp = g_ncac[n*3+2];
    #pragma unroll
    for (int a = 0; a < 3; a++) {
        float4 p = g_ncac[j*3+a];
        float dx=p.x-ca.x, dy=p.y-ca.y, dz=p.z-ca.z;
        g_dist[n*NDIST + k*3 + a] = sqrtf(fmaf(dx,dx, fmaf(dy,dy, dz*dz)));
    }
    {
        float4 p = g_ncac[j*3+2];
        float dx=p.x-np.x, dy=p.y-np.y, dz=p.z-np.z;
        g_dist[n*NDIST + 60 + k] = sqrtf(fmaf(dx,dx, fmaf(dy,dy, dz*dz)));
        float4 p2 = g_ncac[j*3+0];
        float ex2=p2.x-cp.x, ey2=p2.y-cp.y, ez2=p2.z-cp.z;
        g_dist[n*NDIST + 80 + k] = sqrtf(fmaf(ex2,ex2, fmaf(ey2,ey2, ez2*ez2)));
    }
}

// enc[n][d*20 + t] = sin(dist*f_t), enc[n][d*20+10+t] = cos(dist*f_t)
__global__ void enc_kernel() {
    __shared__ float dl[NDIST];
    __shared__ float fl[PDIM/2];
    int n = blockIdx.x;
    int tid = threadIdx.x;
    if (tid < NDIST) dl[tid] = g_dist[n*NDIST+tid];
    if (tid >= 128 && tid < 128+PDIM/2) fl[tid-128] = g_freq[tid-128];
    __syncthreads();
    for (int f = tid; f < NDIST*(PDIM/2); f += 256) {
        int d = f / 10;
        int t = f - d*10;
        float sv, cv;
        sincos_poly(dl[d] * fl[t], sv, cv);
        g_enc[n*NFEAT + d*20 + t]      = sv;
        g_enc[n*NFEAT + d*20 + 10 + t] = cv;
    }
}

// copy x (8192x256) into x_ne rows (stride 320), vectorized
__global__ void copyx_kernel(const float* __restrict__ x, float* __restrict__ out) {
    int i = blockIdx.x*256 + threadIdx.x;
    if (i >= NN*64) return;
    int n = i >> 6, c = i & 63;
    float4 v = ((const float4*)x)[i];
    ((float4*)out)[n*80 + c] = v;
}

// ---------------------------------------------------------------------------
// GEMM: C(8192x64) = g_enc(8192x2000) @ g_wt(2000x64)
// ---------------------------------------------------------------------------
#define BK 16
__global__ void gemm_kernel(float* __restrict__ out) {
    __shared__ float As[BK][68];
    __shared__ float Bs[BK][64];
    int tid = threadIdx.x;
    int tx = tid & 15, ty = tid >> 4;
    int m0 = blockIdx.x * 64;
    float acc[4][4];
    #pragma unroll
    for (int a = 0; a < 4; a++)
        #pragma unroll
        for (int b = 0; b < 4; b++) acc[a][b] = 0.f;

    const float* Ag = g_enc + (size_t)m0 * NFEAT;
    for (int kt = 0; kt < NFEAT; kt += BK) {
        #pragma unroll
        for (int i = 0; i < 4; i++) {
            int e = tid + i*256;
            int m = e >> 4, kk = e & 15;
            As[kk][m] = Ag[m*NFEAT + kt + kk];
        }
        #pragma unroll
        for (int i = 0; i < 4; i++) {
            int e = tid + i*256;
            int kk = e >> 6, nn = e & 63;
            Bs[kk][nn] = g_wt[(kt+kk)*NVZ + nn];
        }
        __syncthreads();
        #pragma unroll
        for (int kk = 0; kk < BK; kk++) {
            float4 a = *(const float4*)&As[kk][ty*4];
            float4 b = *(const float4*)&Bs[kk][tx*4];
            float av[4] = {a.x,a.y,a.z,a.w};
            float bv[4] = {b.x,b.y,b.z,b.w};
            #pragma unroll
            for (int i = 0; i < 4; i++)
                #pragma unroll
                for (int jj = 0; jj < 4; jj++)
                    acc[i][jj] = fmaf(av[i], bv[jj], acc[i][jj]);
        }
        __syncthreads();
    }
    #pragma unroll
    for (int i = 0; i < 4; i++) {
        int m = m0 + ty*4 + i;
        #pragma unroll
        for (int jj = 0; jj < 4; jj++)
            out[m*(FZ+NVZ) + FZ + tx*4 + jj] = acc[i][jj];
    }
}

extern "C" void kernel_launch(void* const* d_in, const int* in_sizes, int n_in,
                              void* d_out, int out_size) {
    const float* x    = (const float*)d_in[0];
    const float* aff  = (const float*)d_in[1];
    const float* nw   = (const float*)d_in[2];
    const float* lit  = (const float*)d_in[3];
    const void*  mask = d_in[4];
    float* out = (float*)d_out;

    detect_kernel<<<1, 256>>>((const unsigned int*)mask);
    wt_kernel<<<(NVZ*NFEAT + 255)/256, 256>>>(nw);
    setup_kernel<<<(NN+255)/256, 256>>>(aff, lit, mask, out);
    knn_kernel<<<NN/8, 256>>>(out);
    geom_kernel<<<NN, 32>>>(aff, out);
    enc_kernel<<<NN, 256>>>();
    copyx_kernel<<<(NN*64 + 255)/256, 256>>>(x, out);
    gemm_kernel<<<NN/64, 256>>>(out);
}

// round 10
// speedup vs baseline: 2.1537x; 1.0602x over previous
#include <cuda_runtime.h>
#include <math.h>

#define NN      8192
#define KZ      20
#define PDIM    20
#define NVZ     64
#define NUMPROT 20
#define FZ      256
#define NFEAT   2000
#define NDIST   100

// output layout: tuple members concatenated, float32
#define OFF_POS (NN*(FZ+NVZ))
#define OFF_NP  (OFF_POS + NN*3)
#define OFF_ND  (OFF_NP  + NN*KZ*3)
#define OFF_EI  (OFF_ND  + NN*KZ*PDIM)
#define OFF_FEI (OFF_EI  + NN*KZ)

typedef unsigned long long u64;

// device scratch (allocation-free rule -> static globals)
__device__ float4 g_pos4[NN];
__device__ float4 g_ncac[NN*3];
__device__ int    g_edge[NN*KZ];
__device__ float  g_wt[NFEAT*NVZ];
__device__ float  g_enc[NN*NFEAT];
__device__ float  g_freq[PDIM/2];
__device__ int    g_mask_kind;

__device__ __forceinline__ u64 ffma2(u64 a, u64 b, u64 c) {
    u64 d;
    asm("fma.rn.f32x2 %0, %1, %2, %3;" : "=l"(d) : "l"(a), "l"(b), "l"(c));
    return d;
}
__device__ __forceinline__ u64 pack2(float x, float y) {
    u64 r;
    asm("mov.b64 %0, {%1, %2};" : "=l"(r) : "f"(x), "f"(y));
    return r;
}
__device__ __forceinline__ void unpack2(u64 v, float& x, float& y) {
    asm("mov.b64 {%0, %1}, %2;" : "=f"(x), "=f"(y) : "l"(v));
}

// ---------------------------------------------------------------------------
// FMA-pipe sincos (abs err < 4e-6 for |x| < 25)
// ---------------------------------------------------------------------------
__device__ __forceinline__ void sincos_poly(float x, float& so, float& co) {
    float q = rintf(x * 0.6366197723675814f);
    int iq = (int)q;
    float r = fmaf(-q, 1.57079637050628662109375f, x);
    r = fmaf(-q, -4.37113900018624283e-8f, r);
    float r2 = r * r;
    float ps = fmaf(-1.9841270114e-4f, r2, 8.3333337680e-3f);
    ps = fmaf(ps, r2, -1.6666667163e-1f);
    float sinr = fmaf(ps * r2, r, r);
    float pc = fmaf(-1.3888889225e-3f, r2, 4.1666667908e-2f);
    pc = fmaf(pc, r2, -0.5f);
    float cosr = fmaf(pc, r2, 1.0f);
    int qq = iq & 3;
    float s_ = (qq & 1) ? cosr : sinr;
    float c_ = (qq & 1) ? sinr : cosr;
    if (qq == 1 || qq == 2) c_ = -c_;
    if (qq >= 2) s_ = -s_;
    so = s_; co = c_;
}

// ---------------------------------------------------------------------------
// Classify prot_mask storage: 0=int32(0/1 words), 1=uint8, 2=float32.
// ---------------------------------------------------------------------------
__global__ void detect_kernel(const unsigned int* __restrict__ m) {
    __shared__ int red[256];
    int t = threadIdx.x;
    int code = 0;
    for (int i = t; i < 2048; i += 256) {
        unsigned w = m[i];
        if (w == 0x3F800000u) code = 2;
        else if (w != 0u && w != 1u) code = max(code, 1);
    }
    red[t] = code; __syncthreads();
    for (int s = 128; s > 0; s >>= 1) {
        if (t < s) red[t] = max(red[t], red[t+s]);
        __syncthreads();
    }
    if (t == 0) g_mask_kind = red[0];
    if (t < PDIM/2) g_freq[t] = (float)exp(-0.39120230054281463 * (double)t);
}

// ne_weight (64,2000) -> g_wt (2000,64)
__global__ void wt_kernel(const float* __restrict__ w) {
    int idx = blockIdx.x*256 + threadIdx.x;
    if (idx >= NVZ*NFEAT) return;
    int o = idx / NFEAT, f = idx - o*NFEAT;
    g_wt[f*NVZ + o] = w[idx];
}

// per-node: pos4 (pos + |p|^2, plain asc rounding), ncac atoms, positions out
__global__ void setup_kernel(const float* __restrict__ aff,
                             const float* __restrict__ lit,
                             const void*  __restrict__ maskp,
                             float* __restrict__ out) {
    int i = blockIdx.x*256 + threadIdx.x;
    if (i >= NN) return;
    const float* A = aff + i*12;
    float r0=A[0], r1=A[1], r2=A[2],  tx=A[3];
    float r3=A[4], r4=A[5], r5=A[6],  ty=A[7];
    float r6=A[8], r7=A[9], r8=A[10], tz=A[11];
    float n2 = __fadd_rn(__fadd_rn(__fmul_rn(tx,tx), __fmul_rn(ty,ty)),
                         __fmul_rn(tz,tz));
    g_pos4[i] = make_float4(tx,ty,tz,n2);
    out[OFF_POS+i*3+0]=tx; out[OFF_POS+i*3+1]=ty; out[OFF_POS+i*3+2]=tz;

    int kind = g_mask_kind;
    bool mk;
    if (kind == 1)      mk = ((const unsigned char*)maskp)[i] != 0;
    else if (kind == 2) mk = ((const float*)maskp)[i] != 0.0f;
    else                mk = ((const int*)maskp)[i] != 0;
    const float* L = lit + (mk ? 0 : NUMPROT)*9;
    #pragma unroll
    for (int a = 0; a < 3; a++) {
        float lx=L[a*3+0], ly=L[a*3+1], lz=L[a*3+2];
        float px = fmaf(r0,lx, fmaf(r1,ly, r2*lz)) + tx;
        float py = fmaf(r3,lx, fmaf(r4,ly, r5*lz)) + ty;
        float pz = fmaf(r6,lx, fmaf(r7,ly, r8*lz)) + tz;
        g_ncac[i*3+a] = make_float4(px,py,pz,0.f);
    }
}

// ---------------------------------------------------------------------------
// kNN: warp-cooperative ballot-insert top-20, cached warp-uniform threshold.
// d2 bits FROZEN: dot = fma(z,z', fma(y,y', rn(x*x')));
//                 d2  = rn(n2i + fma(-2,dot,n2j))
// List sorted lexicographically by (d2, index) == lax.top_k stable order.
// ---------------------------------------------------------------------------
#define KTILE 2048
__global__ void __launch_bounds__(256) knn_kernel(float* __restrict__ out) {
    __shared__ float4 tile[KTILE];
    const unsigned FULL = 0xffffffffu;
    int warp = threadIdx.x >> 5;
    int lane = threadIdx.x & 31;
    int q = blockIdx.x*8 + warp;
    float4 P = g_pos4[q];
    const float INF = __int_as_float(0x7f800000);
    float dist = INF;
    int   idx  = 0x7FFFFFFF;
    float thrd = INF;          // cached slot-19 value (warp-uniform)
    int   thri = 0x7FFFFFFF;   // cached slot-19 index

    for (int t0 = 0; t0 < NN; t0 += KTILE) {
        __syncthreads();
        for (int i = threadIdx.x; i < KTILE; i += 256) tile[i] = g_pos4[t0+i];
        __syncthreads();
        #pragma unroll 4
        for (int b = 0; b < KTILE; b += 32) {
            int j = t0 + b + lane;
            float4 c = tile[b + lane];
            float dot = __fmaf_rn(P.z, c.z,
                        __fmaf_rn(P.y, c.y, __fmul_rn(P.x, c.x)));
            float d2  = __fadd_rn(P.w, __fmaf_rn(-2.0f, dot, c.w));
            bool qual = (j != q) &&
                        (d2 < thrd || (d2 == thrd && j < thri));
            unsigned bal = __ballot_sync(FULL, qual);
            if (bal) {
                do {
                    int src = __ffs(bal) - 1; bal &= bal - 1;
                    float cd = __shfl_sync(FULL, d2, src);
                    int   ci = t0 + b + src;
                    unsigned mlt = __ballot_sync(FULL,
                        (dist < cd) || (dist == cd && idx < ci)) & 0xFFFFFu;
                    int p = __popc(mlt);
                    if (p < 20) {
                        float nd = __shfl_up_sync(FULL, dist, 1);
                        int   ni = __shfl_up_sync(FULL, idx, 1);
                        if (lane >= p && lane < 20) {
                            dist = (lane == p) ? cd : nd;
                            idx  = (lane == p) ? ci : ni;
                        }
                    }
                } while (bal);
                thrd = __shfl_sync(FULL, dist, 19);
                thri = __shfl_sync(FULL, idx, 19);
            }
        }
    }
    if (lane < KZ) {
        g_edge[q*KZ+lane] = idx;
        out[OFF_EI  + q*KZ + lane] = (float)idx;
        out[OFF_FEI + q*KZ + lane] = (float)idx;
        out[OFF_FEI + NN*KZ + q*KZ + lane] = (float)q;
    }
}

// ---------------------------------------------------------------------------
// Merged per-node geometry + encoding. 128 threads per node:
// threads 0..19 do edge geometry (writes + backbone distances into smem),
// then all 128 compute the 1000 sincos pairs of enc.
// ---------------------------------------------------------------------------
__global__ void __launch_bounds__(128) geom_enc_kernel(const float* __restrict__ aff,
                                                       float* __restrict__ out) {
    __shared__ float dl[NDIST];
    __shared__ float fl[PDIM/2];
    int n = blockIdx.x;
    int tid = threadIdx.x;
    if (tid < PDIM/2) fl[tid] = g_freq[tid];
    __syncthreads();

    if (tid < KZ) {
        int k = tid;
        const float* A = aff + n*12;
        float r0=A[0], r1=A[1], r2=A[2],  tx=A[3];
        float r3=A[4], r4=A[5], r5=A[6],  ty=A[7];
        float r6=A[8], r7=A[9], r8=A[10], tz=A[11];
        int j = g_edge[n*KZ+k];
        float4 nb = g_pos4[j];
        float vx = nb.x - tx, vy = nb.y - ty, vz = nb.z - tz;
        float ex = fmaf(r0,vx, fmaf(r3,vy, r6*vz));
        float ey = fmaf(r1,vx, fmaf(r4,vy, r7*vz));
        float ez = fmaf(r2,vx, fmaf(r5,vy, r8*vz));
        int eb = (n*KZ+k)*3;
        out[OFF_NP+eb+0]=ex; out[OFF_NP+eb+1]=ey; out[OFF_NP+eb+2]=ez;
        float nrm = sqrtf(fmaf(ex,ex, fmaf(ey,ey, ez*ez)));
        int db = (n*KZ+k)*PDIM;
        #pragma unroll
        for (int t = 0; t < PDIM/2; t++) {
            float sv, cv;
            sincos_poly(nrm * fl[t], sv, cv);
            out[OFF_ND+db+t]    = sv;
            out[OFF_ND+db+10+t] = cv;
        }
        float4 ca = g_ncac[n*3+1], np = g_ncac[n*3+0], cp = g_ncac[n*3+2];
        #pragma unroll
        for (int a = 0; a < 3; a++) {
            float4 p = g_ncac[j*3+a];
            float dx=p.x-ca.x, dy=p.y-ca.y, dz=p.z-ca.z;
            dl[k*3 + a] = sqrtf(fmaf(dx,dx, fmaf(dy,dy, dz*dz)));
        }
        {
            float4 p = g_ncac[j*3+2];
            float dx=p.x-np.x, dy=p.y-np.y, dz=p.z-np.z;
            dl[60 + k] = sqrtf(fmaf(dx,dx, fmaf(dy,dy, dz*dz)));
            float4 p2 = g_ncac[j*3+0];
            float ex2=p2.x-cp.x, ey2=p2.y-cp.y, ez2=p2.z-cp.z;
            dl[80 + k] = sqrtf(fmaf(ex2,ex2, fmaf(ey2,ey2, ez2*ez2)));
        }
    }
    __syncthreads();

    for (int f = tid; f < NDIST*(PDIM/2); f += 128) {
        int d = f / 10;
        int t = f - d*10;
        float sv, cv;
        sincos_poly(dl[d] * fl[t], sv, cv);
        g_enc[n*NFEAT + d*20 + t]      = sv;
        g_enc[n*NFEAT + d*20 + 10 + t] = cv;
    }
}

// ---------------------------------------------------------------------------
// GEMM (f32x2 packed FMA) + fused x-copy.
// C(8192x64) = g_enc(8192x2000) @ g_wt(2000x64); per-element fp32 fma
// sequence identical to scalar version (k ascending) -> bitwise same.
// ---------------------------------------------------------------------------
#define BK 16
__global__ void __launch_bounds__(256) gemm_kernel(const float* __restrict__ x,
                                                   float* __restrict__ out) {
    __shared__ float As[BK][68];
    __shared__ float Bs[BK][64];
    int tid = threadIdx.x;
    int tx = tid & 15, ty = tid >> 4;
    int m0 = blockIdx.x * 64;

    // fused copyx: rows m0..m0+63, 256 floats each (4096 float4 / 256 thr)
    {
        const float4* xs = (const float4*)(x) + (size_t)m0*64;
        float4* od = (float4*)out;
        #pragma unroll
        for (int i = 0; i < 16; i++) {
            int e = tid + i*256;          // 0..4095
            int r = e >> 6, c = e & 63;
            od[(size_t)(m0+r)*80 + c] = xs[e];
        }
    }

    u64 acc[4][2];
    #pragma unroll
    for (int a = 0; a < 4; a++) { acc[a][0] = pack2(0.f,0.f); acc[a][1] = pack2(0.f,0.f); }

    const float* Ag = g_enc + (size_t)m0 * NFEAT;
    for (int kt = 0; kt < NFEAT; kt += BK) {
        #pragma unroll
        for (int i = 0; i < 4; i++) {
            int e = tid + i*256;
            int m = e >> 4, kk = e & 15;
            As[kk][m] = Ag[m*NFEAT + kt + kk];
        }
        #pragma unroll
        for (int i = 0; i < 4; i++) {
            int e = tid + i*256;
            int kk = e >> 6, nn = e & 63;
            Bs[kk][nn] = g_wt[(kt+kk)*NVZ + nn];
        }
        __syncthreads();
        #pragma unroll
        for (int kk = 0; kk < BK; kk++) {
            float4 a = *(const float4*)&As[kk][ty*4];
            const u64* bp = (const u64*)&Bs[kk][tx*4];
            u64 b01 = bp[0], b23 = bp[1];
            float av[4] = {a.x,a.y,a.z,a.w};
            #pragma unroll
            for (int i = 0; i < 4; i++) {
                u64 ai = pack2(av[i], av[i]);
                acc[i][0] = ffma2(ai, b01, acc[i][0]);
                acc[i][1] = ffma2(ai, b23, acc[i][1]);
            }
        }
        __syncthreads();
    }
    #pragma unroll
    for (int i = 0; i < 4; i++) {
        int m = m0 + ty*4 + i;
        float c0,c1,c2,c3;
        unpack2(acc[i][0], c0, c1);
        unpack2(acc[i][1], c2, c3);
        float* od = out + (size_t)m*(FZ+NVZ) + FZ + tx*4;
        od[0]=c0; od[1]=c1; od[2]=c2; od[3]=c3;
    }
}

extern "C" void kernel_launch(void* const* d_in, const int* in_sizes, int n_in,
                              void* d_out, int out_size) {
    const float* x    = (const float*)d_in[0];
    const float* aff  = (const float*)d_in[1];
    const float* nw   = (const float*)d_in[2];
    const float* lit  = (const float*)d_in[3];
    const void*  mask = d_in[4];
    float* out = (float*)d_out;

    detect_kernel<<<1, 256>>>((const unsigned int*)mask);
    wt_kernel<<<(NVZ*NFEAT + 255)/256, 256>>>(nw);
    setup_kernel<<<(NN+255)/256, 256>>>(aff, lit, mask, out);
    knn_kernel<<<NN/8, 256>>>(out);
    geom_enc_kernel<<<NN, 128>>>(aff, out);
    gemm_kernel<<<NN/64, 256>>>(x, out);
}